// round 4
// baseline (speedup 1.0000x reference)
#include <cuda_runtime.h>
#include <cuda_bf16.h>

// Device-global scratch accumulators (no allocation allowed in kernel_launch).
__device__ double g_acc[2];   // [0]=sum CE over selected, [1]=sum smoothL1 rows over positive

__global__ void mbl_zero_kernel() {
    g_acc[0] = 0.0;
    g_acc[1] = 0.0;
}

__device__ __forceinline__ float smooth_l1(float d) {
    float ad = fabsf(d);
    return (ad < 1.0f) ? 0.5f * d * d : ad - 0.5f;
}

__device__ __forceinline__ void row_work(int lbl, float cx, float cy,
                                         const float4* __restrict__ rout,
                                         const float4* __restrict__ reg_t,
                                         int i, double& c_acc, double& r_acc) {
    // classification: CE on selected rows (lbl==0 or lbl==1)
    if (lbl == 0 || lbl == 1) {
        float m  = fmaxf(cx, cy);
        float mn = fminf(cx, cy);
        float lse = m + log1pf(expf(mn - m));     // stable log-sum-exp
        float xl  = (lbl == 1) ? cy : cx;
        c_acc += (double)(lse - xl);
    }
    // regression: only for positive rows — predicated loads skip ~44% of sectors
    if (lbl == 1) {
        float4 r = rout[i];
        float4 t = reg_t[i];
        float s = smooth_l1(r.x - t.x) + smooth_l1(r.y - t.y)
                + smooth_l1(r.z - t.z) + smooth_l1(r.w - t.w);
        r_acc += (double)(s * 0.25f);
    }
}

__global__ void __launch_bounds__(256)
mbl_reduce_kernel(const float4* __restrict__ cout4,   // 2 rows per float4
                  const float4* __restrict__ rout,
                  const int4*   __restrict__ cls4,    // 4 labels per int4 (int32!)
                  const float4* __restrict__ reg_t,
                  int n) {
    double c_acc = 0.0;
    double r_acc = 0.0;

    int n4 = n >> 2;  // groups of 4 rows
    int idx = blockIdx.x * blockDim.x + threadIdx.x;
    int stride = gridDim.x * blockDim.x;

    for (int g = idx; g < n4; g += stride) {
        int4 lbl = cls4[g];                 // labels for rows 4g..4g+3
        float4 c01 = cout4[2 * g];          // cout rows 4g, 4g+1
        float4 c23 = cout4[2 * g + 1];      // cout rows 4g+2, 4g+3
        int base = 4 * g;
        row_work(lbl.x, c01.x, c01.y, rout, reg_t, base + 0, c_acc, r_acc);
        row_work(lbl.y, c01.z, c01.w, rout, reg_t, base + 1, c_acc, r_acc);
        row_work(lbl.z, c23.x, c23.y, rout, reg_t, base + 2, c_acc, r_acc);
        row_work(lbl.w, c23.z, c23.w, rout, reg_t, base + 3, c_acc, r_acc);
    }

    // scalar tail (n not divisible by 4)
    const int*    cls  = (const int*)cls4;
    const float2* cout = (const float2*)cout4;
    for (int i = n4 * 4 + idx; i < n; i += stride) {
        int lbl = cls[i];
        float2 c = cout[i];
        row_work(lbl, c.x, c.y, rout, reg_t, i, c_acc, r_acc);
    }

    // ---- block reduction ----
    #pragma unroll
    for (int off = 16; off > 0; off >>= 1) {
        c_acc += __shfl_down_sync(0xFFFFFFFFu, c_acc, off);
        r_acc += __shfl_down_sync(0xFFFFFFFFu, r_acc, off);
    }

    __shared__ double s_c[8];
    __shared__ double s_r[8];
    int lane = threadIdx.x & 31;
    int wid  = threadIdx.x >> 5;
    if (lane == 0) { s_c[wid] = c_acc; s_r[wid] = r_acc; }
    __syncthreads();

    if (wid == 0) {
        int nwarps = blockDim.x >> 5;
        double cc = (lane < nwarps) ? s_c[lane] : 0.0;
        double rr = (lane < nwarps) ? s_r[lane] : 0.0;
        #pragma unroll
        for (int off = 4; off > 0; off >>= 1) {
            cc += __shfl_down_sync(0xFFFFFFFFu, cc, off);
            rr += __shfl_down_sync(0xFFFFFFFFu, rr, off);
        }
        if (lane == 0) {
            atomicAdd(&g_acc[0], cc);
            atomicAdd(&g_acc[1], rr);
        }
    }
}

__global__ void mbl_finalize_kernel(float* __restrict__ out) {
    double closs = g_acc[0] / 64.0;
    double rloss = g_acc[1] / 16.0;
    out[0] = (float)closs;
    out[1] = (float)rloss;
    out[2] = (float)(closs + 10.0 * rloss);
}

extern "C" void kernel_launch(void* const* d_in, const int* in_sizes, int n_in,
                              void* d_out, int out_size) {
    const float4* cout  = (const float4*)d_in[0];   // [N,2] f32 (2 rows per float4)
    const float4* rout  = (const float4*)d_in[1];   // [N,4] f32
    const int4*   cls_t = (const int4*)d_in[2];     // [N] int32 (JAX x64 disabled)
    const float4* reg_t = (const float4*)d_in[3];   // [N,4] f32
    float* out = (float*)d_out;

    int n = in_sizes[2];  // N

    mbl_zero_kernel<<<1, 1>>>();

    const int threads = 256;
    int groups = (n + 3) / 4;
    int blocks = (groups + threads - 1) / threads;
    if (blocks > 1184) blocks = 1184;  // 148 SMs * 8 blocks
    mbl_reduce_kernel<<<blocks, threads>>>(cout, rout, cls_t, reg_t, n);

    mbl_finalize_kernel<<<1, 1>>>(out);
}

// round 9
// speedup vs baseline: 1.8501x; 1.8501x over previous
#include <cuda_runtime.h>
#include <cuda_bf16.h>

// Per-block partial sums + completion counter (no allocation allowed).
#define MAX_BLOCKS 2048
__device__ double g_partial_c[MAX_BLOCKS];
__device__ double g_partial_r[MAX_BLOCKS];
__device__ unsigned int g_done = 0;   // zero at module load; last block resets it

__device__ __forceinline__ float smooth_l1(float d) {
    float ad = fabsf(d);
    return (ad < 1.0f) ? 0.5f * d * d : ad - 0.5f;
}

__device__ __forceinline__ void row_work(int lbl, float cx, float cy,
                                         const float4* __restrict__ rout,
                                         const float4* __restrict__ reg_t,
                                         int i, float& c_acc, float& r_acc) {
    // classification: CE on selected rows (lbl==0 or lbl==1)
    if (lbl == 0 || lbl == 1) {
        float m  = fmaxf(cx, cy);
        float mn = fminf(cx, cy);
        float lse = m + log1pf(expf(mn - m));   // stable log-sum-exp
        float xl  = (lbl == 1) ? cy : cx;
        c_acc += (lse - xl);
    }
    // regression: only positive rows — predicated loads skip ~44% of sectors
    if (lbl == 1) {
        float4 r = rout[i];
        float4 t = reg_t[i];
        float s = smooth_l1(r.x - t.x) + smooth_l1(r.y - t.y)
                + smooth_l1(r.z - t.z) + smooth_l1(r.w - t.w);
        r_acc += s * 0.25f;
    }
}

__global__ void __launch_bounds__(256)
mbl_fused_kernel(const float4* __restrict__ cout4,   // 2 rows per float4
                 const float4* __restrict__ rout,
                 const int4*   __restrict__ cls4,    // 4 int32 labels per int4
                 const float4* __restrict__ reg_t,
                 int n,
                 float* __restrict__ out) {
    float c_acc = 0.0f;
    float r_acc = 0.0f;

    int n4 = n >> 2;
    int idx = blockIdx.x * blockDim.x + threadIdx.x;
    int stride = gridDim.x * blockDim.x;

    for (int g = idx; g < n4; g += stride) {
        int4   lbl = cls4[g];
        float4 c01 = cout4[2 * g];
        float4 c23 = cout4[2 * g + 1];
        int base = 4 * g;
        row_work(lbl.x, c01.x, c01.y, rout, reg_t, base + 0, c_acc, r_acc);
        row_work(lbl.y, c01.z, c01.w, rout, reg_t, base + 1, c_acc, r_acc);
        row_work(lbl.z, c23.x, c23.y, rout, reg_t, base + 2, c_acc, r_acc);
        row_work(lbl.w, c23.z, c23.w, rout, reg_t, base + 3, c_acc, r_acc);
    }

    // scalar tail (n % 4 != 0)
    const int*    cls  = (const int*)cls4;
    const float2* cout = (const float2*)cout4;
    for (int i = n4 * 4 + idx; i < n; i += stride) {
        int lbl = cls[i];
        float2 c = cout[i];
        row_work(lbl, c.x, c.y, rout, reg_t, i, c_acc, r_acc);
    }

    // ---- block reduction: float shuffles, double at warp-leader granularity ----
    #pragma unroll
    for (int off = 16; off > 0; off >>= 1) {
        c_acc += __shfl_down_sync(0xFFFFFFFFu, c_acc, off);
        r_acc += __shfl_down_sync(0xFFFFFFFFu, r_acc, off);
    }

    __shared__ double s_c[8];
    __shared__ double s_r[8];
    __shared__ int s_last;
    int lane = threadIdx.x & 31;
    int wid  = threadIdx.x >> 5;
    if (lane == 0) { s_c[wid] = (double)c_acc; s_r[wid] = (double)r_acc; }
    __syncthreads();

    if (threadIdx.x == 0) {
        double cc = 0.0, rr = 0.0;
        #pragma unroll
        for (int w = 0; w < 8; w++) { cc += s_c[w]; rr += s_r[w]; }
        g_partial_c[blockIdx.x] = cc;
        g_partial_r[blockIdx.x] = rr;
        __threadfence();
        unsigned int t = atomicAdd(&g_done, 1u);
        s_last = (t == gridDim.x - 1) ? 1 : 0;
    }
    __syncthreads();

    // ---- last block: reduce per-block partials and finalize ----
    if (s_last) {
        __threadfence();
        double cc = 0.0, rr = 0.0;
        for (int i = threadIdx.x; i < gridDim.x; i += blockDim.x) {
            cc += g_partial_c[i];
            rr += g_partial_r[i];
        }
        #pragma unroll
        for (int off = 16; off > 0; off >>= 1) {
            cc += __shfl_down_sync(0xFFFFFFFFu, cc, off);
            rr += __shfl_down_sync(0xFFFFFFFFu, rr, off);
        }
        if (lane == 0) { s_c[wid] = cc; s_r[wid] = rr; }
        __syncthreads();
        if (threadIdx.x == 0) {
            double fc = 0.0, fr = 0.0;
            #pragma unroll
            for (int w = 0; w < 8; w++) { fc += s_c[w]; fr += s_r[w]; }
            double closs = fc / 64.0;
            double rloss = fr / 16.0;
            out[0] = (float)closs;
            out[1] = (float)rloss;
            out[2] = (float)(closs + 10.0 * rloss);
            g_done = 0;   // reset for next graph replay
        }
    }
}

extern "C" void kernel_launch(void* const* d_in, const int* in_sizes, int n_in,
                              void* d_out, int out_size) {
    const float4* cout  = (const float4*)d_in[0];   // [N,2] f32
    const float4* rout  = (const float4*)d_in[1];   // [N,4] f32
    const int4*   cls_t = (const int4*)d_in[2];     // [N] int32
    const float4* reg_t = (const float4*)d_in[3];   // [N,4] f32
    float* out = (float*)d_out;

    int n = in_sizes[2];

    const int threads = 256;
    int groups = (n + 3) / 4;
    int blocks = (groups + threads - 1) / threads;
    if (blocks > 1184) blocks = 1184;   // 148 SMs * 8 blocks -> single wave
    mbl_fused_kernel<<<blocks, threads>>>(cout, rout, cls_t, reg_t, n, out);
}